// round 15
// baseline (speedup 1.0000x reference)
#include <cuda_runtime.h>
#include <cuda_bf16.h>

// Idx2PixelLayer — R14: two row-half passes (L2-resident half captures repeat
// touches, as measured in R6) + full request supply (every lane issues all 4
// table gathers every pass; out-of-half lanes are redirected to a fixed hot
// row so their loads are L2 hits, preserving per-warp in-flight bytes that
// R6's predication destroyed). Stores remain predicated.
//
//  - table loads: ld.global.nc.L2::evict_last.v8.b32 (32B x4 per point)
//  - coords: __ldcs streaming ; out: __stcs streaming

static constexpr int   HW   = 2048;
static constexpr int   CH   = 8;
static constexpr float MODV = 2044.0f;   // H - 4

struct F8 { float v[8]; };

__device__ __forceinline__ F8 ldg_keep32(const float* p) {
    F8 r;
    asm volatile("ld.global.nc.L2::evict_last.v8.b32 {%0,%1,%2,%3,%4,%5,%6,%7}, [%8];"
                 : "=f"(r.v[0]), "=f"(r.v[1]), "=f"(r.v[2]), "=f"(r.v[3]),
                   "=f"(r.v[4]), "=f"(r.v[5]), "=f"(r.v[6]), "=f"(r.v[7])
                 : "l"(p));
    return r;
}

__global__ __launch_bounds__(256)
void idx2pixel_pass(const float* __restrict__ coords,
                    const float* __restrict__ visible,
                    float* __restrict__ out,
                    int n, int rowLo, int rowHi)
{
    int t = blockIdx.x * blockDim.x + threadIdx.x;
    if (t >= n) return;

    float2 co = __ldcs(reinterpret_cast<const float2*>(coords) + t);

    // floor-mod (python semantics) then +1 ; c in [1,2045) < 2048, so the
    // reference's zero-mask (c0 > 2048) can never fire.
    float c0 = fmodf(co.x - 1.0f, MODV); if (c0 < 0.0f) c0 += MODV; c0 += 1.0f;
    float c1 = fmodf(co.y - 1.0f, MODV); if (c1 < 0.0f) c1 += MODV; c1 += 1.0f;

    float f0 = floorf(c0), f1 = floorf(c1);
    float d0 = c0 - f0,   d1 = c1 - f1;
    int i0 = (int)f0, i1 = (int)f1;

    bool active = (i0 >= rowLo) & (i0 < rowHi);
    // Inactive lanes still issue all 4 loads, redirected to a fixed hot row
    // (rowLo / rowLo+1, ~128KB total -> stays L2-resident, ~zero DRAM cost).
    int i0g = active ? i0 : rowLo;

    const float* rowA = visible + ((size_t)i0g * HW + i1) * CH;  // [tl|bl] 64B
    const float* rowB = rowA + (size_t)HW * CH;                  // [tr|br] 64B

    F8 tl = ldg_keep32(rowA);
    F8 bl = ldg_keep32(rowA + 8);
    F8 tr = ldg_keep32(rowB);
    F8 br = ldg_keep32(rowB + 8);

    float o[8];
    #pragma unroll
    for (int k = 0; k < 8; k++) {
        float mt = tr.v[k] + d0 * (tl.v[k] - tr.v[k]);
        float mb = br.v[k] + d0 * (bl.v[k] - br.v[k]);
        o[k] = mb + d1 * (mt - mb);
    }

    if (active) {
        float4* dst = reinterpret_cast<float4*>(out + (size_t)t * CH);
        __stcs(dst + 0, make_float4(o[0], o[1], o[2], o[3]));
        __stcs(dst + 1, make_float4(o[4], o[5], o[6], o[7]));
    }
}

extern "C" void kernel_launch(void* const* d_in, const int* in_sizes, int n_in,
                              void* d_out, int out_size)
{
    const float* coords  = (const float*)d_in[0];   // (N, 2) float32
    const float* visible = (const float*)d_in[1];   // (2048, 2048, 8) float32
    float* out = (float*)d_out;                     // (N, 8) float32

    int n = in_sizes[0] / 2;
    int threads = 256;
    int blocks = (n + threads - 1) / threads;

    // Pass 1: table rows [0,1024) -> resident window rows [0,1025] ~67MB.
    idx2pixel_pass<<<blocks, threads>>>(coords, visible, out, n, 0, 1024);
    // Pass 2: table rows [1024,2046).
    idx2pixel_pass<<<blocks, threads>>>(coords, visible, out, n, 1024, 2046);
}

// round 17
// speedup vs baseline: 1.3570x; 1.3570x over previous
#include <cuda_runtime.h>
#include <cuda_bf16.h>

// Idx2PixelLayer — FINAL (measured-best, ~39.0us, DRAM 62%).
// Bilinear gather from visible[2048,2048,8] at 1e6 random coords.
//
// Optimization history (all measured on GB300, sm_103a):
//   R0  simple 1pt/thread, 8 pre-issued float4 gathers ......... 39.0us  <- best
//   R2  + L2 evict_last/streaming hints, v8.b32 loads .......... 39.5us  neutral
//   R4  2pt/thread (MLP 4->8), regs 38 ......................... 41.7us  worse
//   R3  row binning w/ atomic scatter .......................... 98.4us  worse
//   R6  two row-half passes (predicated) ....................... 43.0us  worse
//   R8  two passes + 2pt/thread (regs 80, occ 30%) ............. 41.4us  worse
//   R12 compact-then-gather dense lists ........................ 70.4us  worse
//   R14 two passes + junk-redirect full supply ................. 53.8us  worse
// Conclusion: traffic is near-compulsory (~198MB vs ~168MB floor); ~62% DRAM
// utilization on random 64B gathers is the row-activation wall. Every
// locality/pipelining restructure lost more to rate than it saved in bytes.

static constexpr int   HW   = 2048;
static constexpr int   CH   = 8;
static constexpr float MODV = 2044.0f;   // H - 4
static constexpr float DIMF = 2048.0f;

__global__ __launch_bounds__(256)
void idx2pixel_kernel(const float* __restrict__ coords,
                      const float* __restrict__ visible,
                      float* __restrict__ out,
                      int n)
{
    int t = blockIdx.x * blockDim.x + threadIdx.x;
    if (t >= n) return;

    float2 co = reinterpret_cast<const float2*>(coords)[t];

    // floor-mod (python semantics) then +1
    float c0 = fmodf(co.x - 1.0f, MODV); if (c0 < 0.0f) c0 += MODV; c0 += 1.0f;
    float c1 = fmodf(co.y - 1.0f, MODV); if (c1 < 0.0f) c1 += MODV; c1 += 1.0f;

    float f0 = floorf(c0), f1 = floorf(c1);
    float d0 = c0 - f0,   d1 = c1 - f1;
    int i0 = (int)f0, i1 = (int)f1;

    // visible[r][col] starts at (r*2048 + col)*8 floats; pixel = 2 float4s.
    // cols i1 and i1+1 are contiguous -> 4 consecutive float4 per row.
    const float4* rowA = reinterpret_cast<const float4*>(
        visible + ((size_t)i0 * HW + i1) * CH);
    const float4* rowB = rowA + (size_t)HW * CH / 4;   // +1 row = +4096 float4

    // Issue all 8 gathers before any compute (max MLP).
    float4 tl0 = rowA[0], tl1 = rowA[1];   // top_left     (i0,   i1)
    float4 bl0 = rowA[2], bl1 = rowA[3];   // bottom_left  (i0,   i1+1)
    float4 tr0 = rowB[0], tr1 = rowB[1];   // top_right    (i0+1, i1)
    float4 br0 = rowB[2], br1 = rowB[3];   // bottom_right (i0+1, i1+1)

    bool zero = (c0 > DIMF);   // reference checks only dim 0 (never true)
    float w0 = zero ? 0.0f : d0;
    float w1 = zero ? 0.0f : d1;

    float o[8];
    {
        const float* tl = &tl0.x; const float* tr = &tr0.x;
        const float* bl = &bl0.x; const float* br = &br0.x;
        #pragma unroll
        for (int k = 0; k < 4; k++) {
            float mt = tr[k] + w0 * (tl[k] - tr[k]);
            float mb = br[k] + w0 * (bl[k] - br[k]);
            o[k] = mb + w1 * (mt - mb);
        }
        tl = &tl1.x; tr = &tr1.x; bl = &bl1.x; br = &br1.x;
        #pragma unroll
        for (int k = 0; k < 4; k++) {
            float mt = tr[k] + w0 * (tl[k] - tr[k]);
            float mb = br[k] + w0 * (bl[k] - br[k]);
            o[4 + k] = mb + w1 * (mt - mb);
        }
    }
    if (zero) {
        #pragma unroll
        for (int k = 0; k < 8; k++) o[k] = 0.0f;
    }

    float4* dst = reinterpret_cast<float4*>(out + (size_t)t * CH);
    dst[0] = make_float4(o[0], o[1], o[2], o[3]);
    dst[1] = make_float4(o[4], o[5], o[6], o[7]);
}

extern "C" void kernel_launch(void* const* d_in, const int* in_sizes, int n_in,
                              void* d_out, int out_size)
{
    const float* coords  = (const float*)d_in[0];   // (N, 2) float32
    const float* visible = (const float*)d_in[1];   // (2048, 2048, 8) float32
    float* out = (float*)d_out;                     // (N, 8) float32

    int n = in_sizes[0] / 2;
    int threads = 256;
    int blocks = (n + threads - 1) / threads;
    idx2pixel_kernel<<<blocks, threads>>>(coords, visible, out, n);
}